// round 5
// baseline (speedup 1.0000x reference)
#include <cuda_runtime.h>

// DecisionGate: g = 1/(1+|x|^4); mask = g>=0.5; dispatched[b,p,:] = (mask? g:0)*act[b,:]
// x [4096,64] f32, act [4096,512] f32. Output f32: g [B*P] | mask [B*P] | dispatched [B*P*D]
//
// R5: persistent 2-row CTAs with software prefetch — overlap row i+1's act/x
// loads + gate math under row i's 64-deep store stream. Double-buffered wsm,
// one __syncthreads per row. Stores stay .cs (R2 winner).

#define B_DIM 4096
#define P_DIM 64
#define D_DIM 512
#define BP    (B_DIM * P_DIM)
#define GRID  (B_DIM / 2)   // 2048 CTAs, rows b and b+GRID each

__global__ __launch_bounds__(128, 16)
void decision_gate_kernel(const float* __restrict__ x,
                          const float* __restrict__ act,
                          float* __restrict__ out) {
    const int t = threadIdx.x;            // 0..127, one float4 of D=512 each

    __shared__ float wsm[2][P_DIM];

    // Row 0 data
    int b = blockIdx.x;
    float4 v = reinterpret_cast<const float4*>(act + (size_t)b * D_DIM)[t];
    float xv = (t < P_DIM) ? x[b * P_DIM + t] : 0.0f;

    #pragma unroll
    for (int i = 0; i < 2; i++) {
        // Prefetch next row's act/x before this row's store burst.
        float4 vn;
        float  xn = 0.0f;
        if (i == 0) {
            const int bn = b + GRID;
            vn = reinterpret_cast<const float4*>(act + (size_t)bn * D_DIM)[t];
            if (t < P_DIM) xn = x[bn * P_DIM + t];
        }

        // Gate math for current row; emit g/mask; stash w.
        if (t < P_DIM) {
            const float x2 = xv * xv;
            const float g  = 1.0f / (1.0f + x2 * x2);
            const bool  m  = (g >= 0.5f);
            out[b * P_DIM + t]      = g;
            out[BP + b * P_DIM + t] = m ? 1.0f : 0.0f;
            wsm[i][t] = m ? g : 0.0f;
        }
        __syncthreads();

        // 64 independent streaming stores: dispatched[b,p,:] = w[p] * v
        float4* __restrict__ base =
            reinterpret_cast<float4*>(out + (size_t)2 * BP
                                          + (size_t)b * P_DIM * D_DIM) + t;
        #pragma unroll
        for (int p = 0; p < P_DIM; p++) {
            const float w = wsm[i][p];    // broadcast LDS, conflict-free
            float4 r;
            r.x = v.x * w;
            r.y = v.y * w;
            r.z = v.z * w;
            r.w = v.w * w;
            __stcs(base + (size_t)p * (D_DIM / 4), r);
        }

        // Rotate in the prefetched row.
        b += GRID;
        v  = vn;
        xv = xn;
    }
}

extern "C" void kernel_launch(void* const* d_in, const int* in_sizes, int n_in,
                              void* d_out, int out_size) {
    const float* x   = (const float*)d_in[0];   // [4096, 64]
    const float* act = (const float*)d_in[1];   // [4096, 512]
    float* out = (float*)d_out;

    decision_gate_kernel<<<GRID, 128>>>(x, act, out);
}

// round 6
// speedup vs baseline: 1.0620x; 1.0620x over previous
#include <cuda_runtime.h>

// DecisionGate: g = 1/(1+|x|^4); mask = g>=0.5; dispatched[b,p,:] = (mask? g:0)*act[b,:]
// x [4096,64] f32, act [4096,512] f32. Output f32: g [B*P] | mask [B*P] | dispatched [B*P*D]
//
// R6: R2 structure (1 row / 128-thread CTA, .cs stores) + per-CTA rotation of
// the p-loop start (p_eff = (p + b) & 63) to de-phase concurrent CTAs' store
// streams across L2 partitions. Warp coalescing unchanged.

#define B_DIM 4096
#define P_DIM 64
#define D_DIM 512
#define BP    (B_DIM * P_DIM)

__global__ __launch_bounds__(128, 16)
void decision_gate_kernel(const float* __restrict__ x,
                          const float* __restrict__ act,
                          float* __restrict__ out) {
    const int b = blockIdx.x;
    const int t = threadIdx.x;            // 0..127, one float4 of D=512 each

    // Each thread owns one float4 of act[b] for the whole CTA lifetime.
    const float4 v = reinterpret_cast<const float4*>(act + (size_t)b * D_DIM)[t];

    // Threads 0..63 compute the 64 gate values; emit g and mask; stash w in smem.
    __shared__ float wsm[P_DIM];
    if (t < P_DIM) {
        const float xv = x[b * P_DIM + t];
        const float x2 = xv * xv;
        const float g  = 1.0f / (1.0f + x2 * x2);
        const bool  m  = (g >= 0.5f);
        out[b * P_DIM + t]      = g;
        out[BP + b * P_DIM + t] = m ? 1.0f : 0.0f;
        wsm[t] = m ? g : 0.0f;
    }
    __syncthreads();

    // 64 independent streaming stores per thread, starting at a per-CTA
    // rotated offset so concurrent CTAs hit different L2 slices at any instant.
    float4* __restrict__ base =
        reinterpret_cast<float4*>(out + (size_t)2 * BP + (size_t)b * P_DIM * D_DIM) + t;

    #pragma unroll
    for (int p = 0; p < P_DIM; p++) {
        const int pe = (p + b) & (P_DIM - 1);
        const float w = wsm[pe];          // broadcast LDS, conflict-free
        float4 r;
        r.x = v.x * w;
        r.y = v.y * w;
        r.z = v.z * w;
        r.w = v.w * w;
        __stcs(base + (size_t)pe * (D_DIM / 4), r);
    }
}

extern "C" void kernel_launch(void* const* d_in, const int* in_sizes, int n_in,
                              void* d_out, int out_size) {
    const float* x   = (const float*)d_in[0];   // [4096, 64]
    const float* act = (const float*)d_in[1];   // [4096, 512]
    float* out = (float*)d_out;

    decision_gate_kernel<<<B_DIM, 128>>>(x, act, out);
}

// round 7
// speedup vs baseline: 1.0695x; 1.0070x over previous
#include <cuda_runtime.h>

// DecisionGate: g = 1/(1+|x|^4); mask = g>=0.5; dispatched[b,p,:] = (mask? g:0)*act[b,:]
// x [4096,64] f32, act [4096,512] f32. Output f32: g [B*P] | mask [B*P] | dispatched [B*P*D]
//
// FINAL (R7 = R2 form): 1 batch row per 128-thread CTA; act row held in
// registers (one float4/thread); 64 gate values in smem; 64 independent
// .cs streaming STG.128 per thread. Measured at the store-path roofline
// (~6.4 TB/s effective external write stream); R3-R6 established that store
// policy, grid shape, prefetch, and L2 de-phasing are all neutral or worse.

#define B_DIM 4096
#define P_DIM 64
#define D_DIM 512
#define BP    (B_DIM * P_DIM)

__global__ __launch_bounds__(128, 16)
void decision_gate_kernel(const float* __restrict__ x,
                          const float* __restrict__ act,
                          float* __restrict__ out) {
    const int b = blockIdx.x;
    const int t = threadIdx.x;            // 0..127, one float4 of D=512 each

    // Each thread owns one float4 of act[b] for the whole CTA lifetime.
    const float4 v = reinterpret_cast<const float4*>(act + (size_t)b * D_DIM)[t];

    // Threads 0..63 compute the 64 gate values; emit g and mask; stash w in smem.
    __shared__ float wsm[P_DIM];
    if (t < P_DIM) {
        const float xv = x[b * P_DIM + t];
        const float x2 = xv * xv;
        const float g  = 1.0f / (1.0f + x2 * x2);
        const bool  m  = (g >= 0.5f);
        __stcs(&out[b * P_DIM + t], g);
        __stcs(&out[BP + b * P_DIM + t], m ? 1.0f : 0.0f);
        wsm[t] = m ? g : 0.0f;
    }
    __syncthreads();

    // 64 independent streaming stores per thread: dispatched[b,p,:] = w[p] * v
    float4* __restrict__ base =
        reinterpret_cast<float4*>(out + (size_t)2 * BP + (size_t)b * P_DIM * D_DIM) + t;

    #pragma unroll
    for (int p = 0; p < P_DIM; p++) {
        const float w = wsm[p];           // broadcast LDS, conflict-free
        float4 r;
        r.x = v.x * w;
        r.y = v.y * w;
        r.z = v.z * w;
        r.w = v.w * w;
        __stcs(base + (size_t)p * (D_DIM / 4), r);
    }
}

extern "C" void kernel_launch(void* const* d_in, const int* in_sizes, int n_in,
                              void* d_out, int out_size) {
    const float* x   = (const float*)d_in[0];   // [4096, 64]
    const float* act = (const float*)d_in[1];   // [4096, 512]
    float* out = (float*)d_out;

    decision_gate_kernel<<<B_DIM, 128>>>(x, act, out);
}